// round 2
// baseline (speedup 1.0000x reference)
#include <cuda_runtime.h>

#define HW      49
#define CCOLS   512
#define CT      128     // c-tile per CTA
#define THREADS 256

typedef unsigned long long u64;

// Packed fp32x2 FMA (Blackwell FFMA2) — only reachable via PTX.
__device__ __forceinline__ u64 fma2(u64 a, u64 b, u64 c) {
    u64 d;
    asm("fma.rn.f32x2 %0, %1, %2, %3;" : "=l"(d) : "l"(a), "l"(b), "l"(c));
    return d;
}

__global__ __launch_bounds__(THREADS)
void bmm_tr_residual_kernel(const float* __restrict__ x,
                            const float* __restrict__ attn,
                            const float* __restrict__ Dm,
                            const float* __restrict__ alpha,
                            float* __restrict__ out)
{
    // attn duplicated per element -> 64-bit broadcast operand loads.
    // __align__(16): these are reinterpreted as u64*/float4* — a bare float
    // array is only 4B-aligned, which faulted in R1.
    __shared__ __align__(16) float sA2[2 * HW * HW + 2];  // padded to 16B multiple
    __shared__ __align__(16) float sD[HW * CT];           // reused as Y[c][p] after compute

    const int n   = blockIdx.y;
    const int c0  = blockIdx.x * CT;
    const int tid = threadIdx.x;

    // ---- stage attn[n] (49x49), duplicated ----
    const float* An = attn + (size_t)n * HW * HW;
    for (int i = tid; i < HW * HW; i += THREADS) {
        float v = An[i];
        sA2[2 * i]     = v;
        sA2[2 * i + 1] = v;
    }

    // ---- stage D[n][:, c0:c0+CT] (49x128) via float4 ----
    const float* Dn = Dm + (size_t)n * HW * CCOLS + c0;
    float4* sD4 = (float4*)sD;
    for (int i = tid; i < HW * (CT / 4); i += THREADS) {
        int q = i / (CT / 4);
        int j = i % (CT / 4);
        sD4[i] = *(const float4*)(Dn + (size_t)q * CCOLS + j * 4);
    }
    __syncthreads();

    // ---- compute: thread tile = 7 p-rows x 2 c-pairs (f32x2) ----
    const int tc = tid & 31;   // c-pair lane: owns pairs {tc, tc+32}
    const int tp = tid >> 5;   // p-row group: owns rows {tp, tp+8, ..., tp+48}

    u64 acc[7][2];
#pragma unroll
    for (int k = 0; k < 7; ++k) { acc[k][0] = 0ull; acc[k][1] = 0ull; }

    const u64* sA64 = (const u64*)sA2;

#pragma unroll 7
    for (int q = 0; q < HW; ++q) {
        u64 b0 = *(const u64*)(sD + q * CT + 2 * tc);        // cols (2tc, 2tc+1)
        u64 b1 = *(const u64*)(sD + q * CT + 2 * tc + 64);   // cols (+64, +65)
#pragma unroll
        for (int k = 0; k < 7; ++k) {
            int p = tp + 8 * k;
            u64 a2 = (p < HW) ? sA64[p * HW + q] : 0ull;     // warp-uniform broadcast
            acc[k][0] = fma2(a2, b0, acc[k][0]);
            acc[k][1] = fma2(a2, b1, acc[k][1]);
        }
    }
    __syncthreads();   // everyone done reading sD — safe to reuse as Y

    // ---- scatter Y into smem as [c][p] so gmem writes are contiguous ----
#pragma unroll
    for (int k = 0; k < 7; ++k) {
        int p = tp + 8 * k;
        if (p < HW) {
#pragma unroll
            for (int w = 0; w < 2; ++w) {
                int pp = tc + 32 * w;
                float lo, hi;
                asm("mov.b64 {%0,%1}, %2;" : "=f"(lo), "=f"(hi) : "l"(acc[k][w]));
                sD[(2 * pp)     * HW + p] = lo;
                sD[(2 * pp + 1) * HW + p] = hi;
            }
        }
    }
    __syncthreads();

    // ---- residual epilogue: out[n, c0:c0+CT, :] is one contiguous CT*HW block ----
    const float  al   = alpha[0];
    const size_t base = (size_t)n * CCOLS * HW + (size_t)c0 * HW;
    const float4* x4  = (const float4*)(x + base);
    const float4* y4  = (const float4*)sD;
    float4*       o4  = (float4*)(out + base);

    for (int i = tid; i < (CT * HW) / 4; i += THREADS) {
        float4 xv = x4[i];
        float4 yv = y4[i];
        float4 ov;
        ov.x = fmaf(al, yv.x, xv.x);
        ov.y = fmaf(al, yv.y, xv.y);
        ov.z = fmaf(al, yv.z, xv.z);
        ov.w = fmaf(al, yv.w, xv.w);
        o4[i] = ov;
    }
}

extern "C" void kernel_launch(void* const* d_in, const int* in_sizes, int n_in,
                              void* d_out, int out_size)
{
    const float* x     = (const float*)d_in[0];
    const float* attn  = (const float*)d_in[1];
    const float* Dm    = (const float*)d_in[2];
    const float* alpha = (const float*)d_in[3];
    float*       out   = (float*)d_out;

    const int N = in_sizes[1] / (HW * HW);   // 2048
    dim3 grid(CCOLS / CT, N);                // (4, 2048)
    bmm_tr_residual_kernel<<<grid, THREADS>>>(x, attn, Dm, alpha, out);
}